// round 1
// baseline (speedup 1.0000x reference)
#include <cuda_runtime.h>

#define N_MAX 100000
#define E_MAX 1600000
#define HID 64

// ---- persistent scratch (no allocation allowed) ----
__device__ int   g_outdeg[N_MAX];
__device__ int   g_indeg[N_MAX];
__device__ int   g_rowptr[N_MAX + 1];
__device__ int   g_cursor[N_MAX];
__device__ int   g_col[E_MAX];
__device__ float g_nsrc[N_MAX];
__device__ float g_ndst[N_MAX];
__device__ float g_hA[N_MAX * HID];
__device__ float g_hB[N_MAX * HID];

// ---------------------------------------------------------------
// K0: zero accumulators (degrees) and the output buffer
// ---------------------------------------------------------------
__global__ void k_init(float* out, int n, int ng) {
    int i = blockIdx.x * blockDim.x + threadIdx.x;
    if (i < n) { g_outdeg[i] = 0; g_indeg[i] = 0; }
    if (i < ng) out[i] = 0.0f;
}

// ---------------------------------------------------------------
// K1: degree counts
// ---------------------------------------------------------------
__global__ void k_deg(const int* __restrict__ src, const int* __restrict__ dst, int e) {
    int i = blockIdx.x * blockDim.x + threadIdx.x;
    if (i < e) {
        atomicAdd(&g_outdeg[src[i]], 1);
        atomicAdd(&g_indeg[dst[i]], 1);
    }
}

// ---------------------------------------------------------------
// K2: norms + h0 = emb[feats] * norm_src   (16 lanes per node, float4)
// ---------------------------------------------------------------
__global__ void k_embed(const int* __restrict__ feats, const float* __restrict__ emb, int n) {
    int t = blockIdx.x * blockDim.x + threadIdx.x;
    int node = t >> 4;
    int l = t & 15;
    if (node >= n) return;
    float ns = rsqrtf(fmaxf((float)g_outdeg[node], 1.0f));
    if (l == 0) {
        g_nsrc[node] = ns;
        g_ndst[node] = rsqrtf(fmaxf((float)g_indeg[node], 1.0f));
    }
    const float4* e4 = (const float4*)emb;
    float4 v = __ldg(&e4[(long)feats[node] * 16 + l]);
    float4 r = make_float4(v.x * ns, v.y * ns, v.z * ns, v.w * ns);
    ((float4*)g_hA)[node * 16 + l] = r;
}

// ---------------------------------------------------------------
// K3: exclusive prefix sum of in-degrees -> rowptr (+ cursor copy)
//     single block of 1024, chunked
// ---------------------------------------------------------------
__global__ void k_prefix(int n) {
    __shared__ int part[1024];
    int t = threadIdx.x;
    int CH = (n + 1023) >> 10;
    int start = t * CH;
    int end = min(start + CH, n);
    int s = 0;
    for (int i = start; i < end; i++) s += g_indeg[i];
    part[t] = s;
    __syncthreads();
    // Hillis-Steele inclusive scan
    for (int off = 1; off < 1024; off <<= 1) {
        int v = (t >= off) ? part[t - off] : 0;
        __syncthreads();
        part[t] += v;
        __syncthreads();
    }
    int run = (t == 0) ? 0 : part[t - 1];
    for (int i = start; i < end; i++) {
        g_rowptr[i] = run;
        g_cursor[i] = run;
        run += g_indeg[i];
    }
    if (start + CH >= n) g_rowptr[n] = run;   // writers all hold total here
}

// ---------------------------------------------------------------
// K4: counting-sort edges by dst into CSR col array
// ---------------------------------------------------------------
__global__ void k_csr(const int* __restrict__ src, const int* __restrict__ dst, int e) {
    int i = blockIdx.x * blockDim.x + threadIdx.x;
    if (i < e) {
        int d = dst[i];
        int p = atomicAdd(&g_cursor[d], 1);
        g_col[p] = src[i];
    }
}

// ---------------------------------------------------------------
// K5/K6: fused SpMM + norm + dense transform (+ final pooling head)
//   16-lane group per node, 4 nodes per group, W in smem.
//   hin rows are already pre-scaled by norm_src.
//   layer 0: A->B   layer 1: B->A   layer 2 (FINAL): A -> pooled dot
// ---------------------------------------------------------------
template <bool FINAL>
__global__ void __launch_bounds__(256)
k_spmm(int layer,
       const float* __restrict__ Wg, const float* __restrict__ bg,
       const float* __restrict__ wreg, const int* __restrict__ gid,
       float* __restrict__ out, int n)
{
    __shared__ float sW[HID * HID];
    __shared__ float sb[HID];
    __shared__ float tbuf[16][4][HID];

    const float* hin  = (layer & 1) ? g_hB : g_hA;
    float*       hout = (layer & 1) ? g_hA : g_hB;
    const float* W = Wg + (long)layer * HID * HID;
    const float* b = bg + (long)layer * HID;

    int tid = threadIdx.x;
    for (int i = tid; i < HID * HID; i += 256) sW[i] = W[i];
    if (tid < HID) sb[tid] = b[tid];
    __syncthreads();

    int gg = (blockIdx.x * 256 + tid) >> 4;   // global group id
    int l  = tid & 15;                        // lane in group (owns cols 4l..4l+3)
    int gl = tid >> 4;                        // group in block
    int base = gg * 4;

    const float4* hin4 = (const float4*)hin;

    // --- gather + dst-norm for 4 nodes ---
    #pragma unroll
    for (int i = 0; i < 4; i++) {
        int node = base + i;
        float4 a = make_float4(0.f, 0.f, 0.f, 0.f);
        if (node < n) {
            int s = g_rowptr[node];
            int e = g_rowptr[node + 1];
            int j = s;
            for (; j + 1 < e; j += 2) {
                int c0 = __ldg(&g_col[j]);
                int c1 = __ldg(&g_col[j + 1]);
                float4 v0 = __ldg(&hin4[(long)c0 * 16 + l]);
                float4 v1 = __ldg(&hin4[(long)c1 * 16 + l]);
                a.x += v0.x + v1.x; a.y += v0.y + v1.y;
                a.z += v0.z + v1.z; a.w += v0.w + v1.w;
            }
            if (j < e) {
                int c0 = __ldg(&g_col[j]);
                float4 v0 = __ldg(&hin4[(long)c0 * 16 + l]);
                a.x += v0.x; a.y += v0.y; a.z += v0.z; a.w += v0.w;
            }
            float nd = g_ndst[node];
            a.x *= nd; a.y *= nd; a.z *= nd; a.w *= nd;
        }
        *(float4*)&tbuf[gl][i][l * 4] = a;
    }
    __syncwarp();

    // --- dense transform: y = t @ W + b (4 nodes amortize W smem reads) ---
    float4 bb = *(const float4*)&sb[l * 4];
    float4 y0 = bb, y1 = bb, y2 = bb, y3 = bb;
    #pragma unroll 4
    for (int k = 0; k < HID; k++) {
        float4 w = *(const float4*)&sW[k * HID + l * 4];
        float t0 = tbuf[gl][0][k];
        float t1 = tbuf[gl][1][k];
        float t2 = tbuf[gl][2][k];
        float t3 = tbuf[gl][3][k];
        y0.x += t0 * w.x; y0.y += t0 * w.y; y0.z += t0 * w.z; y0.w += t0 * w.w;
        y1.x += t1 * w.x; y1.y += t1 * w.y; y1.z += t1 * w.z; y1.w += t1 * w.w;
        y2.x += t2 * w.x; y2.y += t2 * w.y; y2.z += t2 * w.z; y2.w += t2 * w.w;
        y3.x += t3 * w.x; y3.y += t3 * w.y; y3.z += t3 * w.z; y3.w += t3 * w.w;
    }

    float4 ys[4] = {y0, y1, y2, y3};

    if (!FINAL) {
        // write h_next pre-scaled by norm_src for the next gather
        #pragma unroll
        for (int i = 0; i < 4; i++) {
            int node = base + i;
            if (node < n) {
                float ns = g_nsrc[node];
                float4 r = make_float4(ys[i].x * ns, ys[i].y * ns, ys[i].z * ns, ys[i].w * ns);
                ((float4*)hout)[node * 16 + l] = r;
            }
        }
    } else {
        // fused regression head + sum pooling: s = y . W_reg, scatter to graph
        float4 wr = __ldg((const float4*)wreg + l);
        #pragma unroll
        for (int i = 0; i < 4; i++) {
            int node = base + i;
            float p = 0.0f;
            if (node < n)
                p = ys[i].x * wr.x + ys[i].y * wr.y + ys[i].z * wr.z + ys[i].w * wr.w;
            // reduce across the 16-lane group (xor<16 stays in half-warp)
            p += __shfl_xor_sync(0xffffffffu, p, 8);
            p += __shfl_xor_sync(0xffffffffu, p, 4);
            p += __shfl_xor_sync(0xffffffffu, p, 2);
            p += __shfl_xor_sync(0xffffffffu, p, 1);
            if (l == 0 && node < n)
                atomicAdd(&out[gid[node]], p);
        }
    }
}

// ---------------------------------------------------------------
extern "C" void kernel_launch(void* const* d_in, const int* in_sizes, int n_in,
                              void* d_out, int out_size)
{
    const int* feats = (const int*)d_in[0];
    const int* src   = (const int*)d_in[1];
    const int* dst   = (const int*)d_in[2];
    const int* gid   = (const int*)d_in[3];
    int k = 4;
    if (n_in >= 9 && in_sizes[4] == 1) k = 5;   // skip n_graphs scalar if present
    const float* emb  = (const float*)d_in[k];
    const float* Ws   = (const float*)d_in[k + 1];
    const float* bs   = (const float*)d_in[k + 2];
    const float* wreg = (const float*)d_in[k + 3];
    float* out = (float*)d_out;

    int n = in_sizes[0];
    int e = in_sizes[1];
    int ng = out_size;

    k_init<<<(n + 255) / 256, 256>>>(out, n, ng);
    k_deg<<<(e + 255) / 256, 256>>>(src, dst, e);
    k_embed<<<(n * 16 + 255) / 256, 256>>>(feats, emb, n);
    k_prefix<<<1, 1024>>>(n);
    k_csr<<<(e + 255) / 256, 256>>>(src, dst, e);

    int groups = (n + 3) / 4;
    int blocks = (groups + 15) / 16;
    k_spmm<false><<<blocks, 256>>>(0, Ws, bs, wreg, gid, out, n);
    k_spmm<false><<<blocks, 256>>>(1, Ws, bs, wreg, gid, out, n);
    k_spmm<true ><<<blocks, 256>>>(2, Ws, bs, wreg, gid, out, n);
}

// round 2
// speedup vs baseline: 1.5587x; 1.5587x over previous
#include <cuda_runtime.h>

#define N_MAX 100000
#define E_MAX 1600000
#define HID 64
#define SCAN_ELEMS 1024      // elems per scan block (256 thr x 4)
#define SCAN_MAXB 256        // max scan blocks supported (256*1024 = 262144 >= N_MAX)

// ---- persistent scratch (no allocation allowed) ----
__device__ int   g_outdeg[N_MAX];
__device__ int   g_indeg[N_MAX];
__device__ int   g_rowptr[N_MAX + 1];
__device__ int   g_cursor[N_MAX];
__device__ int   g_col[E_MAX];
__device__ int   g_part[SCAN_MAXB];
__device__ float g_nsrc[N_MAX];
__device__ float g_ndst[N_MAX];
__device__ float g_hA[N_MAX * HID];
__device__ float g_hB[N_MAX * HID];

// ---------------------------------------------------------------
// K0: zero accumulators (degrees) and the output buffer
// ---------------------------------------------------------------
__global__ void k_init(float* out, int n, int ng) {
    int i = blockIdx.x * blockDim.x + threadIdx.x;
    if (i < n) { g_outdeg[i] = 0; g_indeg[i] = 0; }
    if (i < ng) out[i] = 0.0f;
}

// ---------------------------------------------------------------
// K1: degree counts
// ---------------------------------------------------------------
__global__ void k_deg(const int* __restrict__ src, const int* __restrict__ dst, int e) {
    int i = blockIdx.x * blockDim.x + threadIdx.x;
    if (i < e) {
        atomicAdd(&g_outdeg[src[i]], 1);
        atomicAdd(&g_indeg[dst[i]], 1);
    }
}

// ---------------------------------------------------------------
// K2: norms + h0 = emb[feats] * norm_src   (16 lanes per node, float4)
// ---------------------------------------------------------------
__global__ void k_embed(const int* __restrict__ feats, const float* __restrict__ emb, int n) {
    int t = blockIdx.x * blockDim.x + threadIdx.x;
    int node = t >> 4;
    int l = t & 15;
    if (node >= n) return;
    float ns = rsqrtf(fmaxf((float)g_outdeg[node], 1.0f));
    if (l == 0) {
        g_nsrc[node] = ns;
        g_ndst[node] = rsqrtf(fmaxf((float)g_indeg[node], 1.0f));
    }
    const float4* e4 = (const float4*)emb;
    float4 v = __ldg(&e4[(long)feats[node] * 16 + l]);
    float4 r = make_float4(v.x * ns, v.y * ns, v.z * ns, v.w * ns);
    ((float4*)g_hA)[node * 16 + l] = r;
}

// ---------------------------------------------------------------
// Multi-block exclusive scan of g_indeg -> g_rowptr / g_cursor
// Phase 1: per-block sums
// ---------------------------------------------------------------
__global__ void __launch_bounds__(256) k_scan_partial(int n) {
    __shared__ int sred[8];
    int b = blockIdx.x, t = threadIdx.x;
    int base = b * SCAN_ELEMS;
    int s = 0;
    #pragma unroll
    for (int k = 0; k < 4; k++) {
        int i = base + t + k * 256;
        if (i < n) s += g_indeg[i];
    }
    #pragma unroll
    for (int o = 16; o; o >>= 1) s += __shfl_xor_sync(0xffffffffu, s, o);
    if ((t & 31) == 0) sred[t >> 5] = s;
    __syncthreads();
    if (t < 8) {
        int v = sred[t];
        #pragma unroll
        for (int o = 4; o; o >>= 1) v += __shfl_xor_sync(0x000000ffu, v, o);
        if (t == 0) g_part[b] = v;
    }
}

// Phase 2: single-block exclusive scan of the <=256 partials; writes total.
__global__ void __launch_bounds__(256) k_scan_mid(int nb, int n) {
    __shared__ int ws[8];
    int t = threadIdx.x;
    int lane = t & 31, w = t >> 5;
    int v = (t < nb) ? g_part[t] : 0;
    int x = v;
    #pragma unroll
    for (int o = 1; o < 32; o <<= 1) {
        int y = __shfl_up_sync(0xffffffffu, x, o);
        if (lane >= o) x += y;
    }
    if (lane == 31) ws[w] = x;
    __syncthreads();
    if (w == 0) {
        int y = (lane < 8) ? ws[lane] : 0;
        #pragma unroll
        for (int o = 1; o < 8; o <<= 1) {
            int z = __shfl_up_sync(0xffffffffu, y, o);
            if (lane >= o) y += z;
        }
        if (lane < 8) ws[lane] = y;
    }
    __syncthreads();
    int incl = x + (w ? ws[w - 1] : 0);
    if (t < nb) g_part[t] = incl - v;          // exclusive block offsets
    if (t == nb - 1) g_rowptr[n] = incl;       // grand total
}

// Phase 3: per-block rescan with offset -> rowptr + cursor
__global__ void __launch_bounds__(256) k_scan_final(int n) {
    __shared__ int ws[8];
    int b = blockIdx.x, t = threadIdx.x;
    int lane = t & 31, w = t >> 5;
    int idx = b * SCAN_ELEMS + 4 * t;

    int4 d = make_int4(0, 0, 0, 0);
    if (idx + 3 < n) d = *(const int4*)&g_indeg[idx];
    else {
        if (idx + 0 < n) d.x = g_indeg[idx + 0];
        if (idx + 1 < n) d.y = g_indeg[idx + 1];
        if (idx + 2 < n) d.z = g_indeg[idx + 2];
        if (idx + 3 < n) d.w = g_indeg[idx + 3];
    }
    int s0 = d.x, s1 = s0 + d.y, s2 = s1 + d.z, s3 = s2 + d.w;

    // exclusive scan of per-thread sums (s3) across the block
    int x = s3;
    #pragma unroll
    for (int o = 1; o < 32; o <<= 1) {
        int y = __shfl_up_sync(0xffffffffu, x, o);
        if (lane >= o) x += y;
    }
    if (lane == 31) ws[w] = x;
    __syncthreads();
    if (w == 0) {
        int y = (lane < 8) ? ws[lane] : 0;
        #pragma unroll
        for (int o = 1; o < 8; o <<= 1) {
            int z = __shfl_up_sync(0xffffffffu, y, o);
            if (lane >= o) y += z;
        }
        if (lane < 8) ws[lane] = y;
    }
    __syncthreads();
    int excl = (x - s3) + (w ? ws[w - 1] : 0) + g_part[b];

    int4 r = make_int4(excl, excl + s0, excl + s1, excl + s2);
    if (idx + 3 < n) {
        *(int4*)&g_rowptr[idx] = r;
        *(int4*)&g_cursor[idx] = r;
    } else {
        if (idx + 0 < n) { g_rowptr[idx + 0] = r.x; g_cursor[idx + 0] = r.x; }
        if (idx + 1 < n) { g_rowptr[idx + 1] = r.y; g_cursor[idx + 1] = r.y; }
        if (idx + 2 < n) { g_rowptr[idx + 2] = r.z; g_cursor[idx + 2] = r.z; }
        if (idx + 3 < n) { g_rowptr[idx + 3] = r.w; g_cursor[idx + 3] = r.w; }
    }
}

// ---------------------------------------------------------------
// K4: counting-sort edges by dst into CSR col array
// ---------------------------------------------------------------
__global__ void k_csr(const int* __restrict__ src, const int* __restrict__ dst, int e) {
    int i = blockIdx.x * blockDim.x + threadIdx.x;
    if (i < e) {
        int d = dst[i];
        int p = atomicAdd(&g_cursor[d], 1);
        g_col[p] = src[i];
    }
}

// ---------------------------------------------------------------
// K5/K6: fused SpMM + norm + dense transform (+ final pooling head)
// ---------------------------------------------------------------
template <bool FINAL>
__global__ void __launch_bounds__(256)
k_spmm(int layer,
       const float* __restrict__ Wg, const float* __restrict__ bg,
       const float* __restrict__ wreg, const int* __restrict__ gid,
       float* __restrict__ out, int n)
{
    __shared__ float sW[HID * HID];
    __shared__ float sb[HID];
    __shared__ float tbuf[16][4][HID];

    const float* hin  = (layer & 1) ? g_hB : g_hA;
    float*       hout = (layer & 1) ? g_hA : g_hB;
    const float* W = Wg + (long)layer * HID * HID;
    const float* b = bg + (long)layer * HID;

    int tid = threadIdx.x;
    for (int i = tid; i < HID * HID; i += 256) sW[i] = W[i];
    if (tid < HID) sb[tid] = b[tid];
    __syncthreads();

    int gg = (blockIdx.x * 256 + tid) >> 4;   // global group id
    int l  = tid & 15;                        // lane in group (owns cols 4l..4l+3)
    int gl = tid >> 4;                        // group in block
    int base = gg * 4;

    const float4* hin4 = (const float4*)hin;

    // --- gather + dst-norm for 4 nodes ---
    #pragma unroll
    for (int i = 0; i < 4; i++) {
        int node = base + i;
        float4 a = make_float4(0.f, 0.f, 0.f, 0.f);
        if (node < n) {
            int s = g_rowptr[node];
            int e = g_rowptr[node + 1];
            int j = s;
            for (; j + 1 < e; j += 2) {
                int c0 = __ldg(&g_col[j]);
                int c1 = __ldg(&g_col[j + 1]);
                float4 v0 = __ldg(&hin4[(long)c0 * 16 + l]);
                float4 v1 = __ldg(&hin4[(long)c1 * 16 + l]);
                a.x += v0.x + v1.x; a.y += v0.y + v1.y;
                a.z += v0.z + v1.z; a.w += v0.w + v1.w;
            }
            if (j < e) {
                int c0 = __ldg(&g_col[j]);
                float4 v0 = __ldg(&hin4[(long)c0 * 16 + l]);
                a.x += v0.x; a.y += v0.y; a.z += v0.z; a.w += v0.w;
            }
            float nd = g_ndst[node];
            a.x *= nd; a.y *= nd; a.z *= nd; a.w *= nd;
        }
        *(float4*)&tbuf[gl][i][l * 4] = a;
    }
    __syncwarp();

    // --- dense transform: y = t @ W + b ---
    float4 bb = *(const float4*)&sb[l * 4];
    float4 y0 = bb, y1 = bb, y2 = bb, y3 = bb;
    #pragma unroll 4
    for (int k = 0; k < HID; k++) {
        float4 w = *(const float4*)&sW[k * HID + l * 4];
        float t0 = tbuf[gl][0][k];
        float t1 = tbuf[gl][1][k];
        float t2 = tbuf[gl][2][k];
        float t3 = tbuf[gl][3][k];
        y0.x += t0 * w.x; y0.y += t0 * w.y; y0.z += t0 * w.z; y0.w += t0 * w.w;
        y1.x += t1 * w.x; y1.y += t1 * w.y; y1.z += t1 * w.z; y1.w += t1 * w.w;
        y2.x += t2 * w.x; y2.y += t2 * w.y; y2.z += t2 * w.z; y2.w += t2 * w.w;
        y3.x += t3 * w.x; y3.y += t3 * w.y; y3.z += t3 * w.z; y3.w += t3 * w.w;
    }

    float4 ys[4] = {y0, y1, y2, y3};

    if (!FINAL) {
        #pragma unroll
        for (int i = 0; i < 4; i++) {
            int node = base + i;
            if (node < n) {
                float ns = g_nsrc[node];
                float4 r = make_float4(ys[i].x * ns, ys[i].y * ns, ys[i].z * ns, ys[i].w * ns);
                ((float4*)hout)[node * 16 + l] = r;
            }
        }
    } else {
        float4 wr = __ldg((const float4*)wreg + l);
        #pragma unroll
        for (int i = 0; i < 4; i++) {
            int node = base + i;
            float p = 0.0f;
            if (node < n)
                p = ys[i].x * wr.x + ys[i].y * wr.y + ys[i].z * wr.z + ys[i].w * wr.w;
            p += __shfl_xor_sync(0xffffffffu, p, 8);
            p += __shfl_xor_sync(0xffffffffu, p, 4);
            p += __shfl_xor_sync(0xffffffffu, p, 2);
            p += __shfl_xor_sync(0xffffffffu, p, 1);
            if (l == 0 && node < n)
                atomicAdd(&out[gid[node]], p);
        }
    }
}

// ---------------------------------------------------------------
extern "C" void kernel_launch(void* const* d_in, const int* in_sizes, int n_in,
                              void* d_out, int out_size)
{
    const int* feats = (const int*)d_in[0];
    const int* src   = (const int*)d_in[1];
    const int* dst   = (const int*)d_in[2];
    const int* gid   = (const int*)d_in[3];
    int k = 4;
    if (n_in >= 9 && in_sizes[4] == 1) k = 5;   // skip n_graphs scalar if present
    const float* emb  = (const float*)d_in[k];
    const float* Ws   = (const float*)d_in[k + 1];
    const float* bs   = (const float*)d_in[k + 2];
    const float* wreg = (const float*)d_in[k + 3];
    float* out = (float*)d_out;

    int n = in_sizes[0];
    int e = in_sizes[1];
    int ng = out_size;

    k_init<<<(n + 255) / 256, 256>>>(out, n, ng);
    k_deg<<<(e + 255) / 256, 256>>>(src, dst, e);
    k_embed<<<(n * 16 + 255) / 256, 256>>>(feats, emb, n);

    int nb = (n + SCAN_ELEMS - 1) / SCAN_ELEMS;   // 98 blocks for n=100k
    k_scan_partial<<<nb, 256>>>(n);
    k_scan_mid<<<1, 256>>>(nb, n);
    k_scan_final<<<nb, 256>>>(n);

    k_csr<<<(e + 255) / 256, 256>>>(src, dst, e);

    int groups = (n + 3) / 4;
    int blocks = (groups + 15) / 16;
    k_spmm<false><<<blocks, 256>>>(0, Ws, bs, wreg, gid, out, n);
    k_spmm<false><<<blocks, 256>>>(1, Ws, bs, wreg, gid, out, n);
    k_spmm<true ><<<blocks, 256>>>(2, Ws, bs, wreg, gid, out, n);
}

// round 3
// speedup vs baseline: 1.6709x; 1.0720x over previous
#include <cuda_runtime.h>
#include <cuda_fp16.h>

#define N_MAX 100000
#define E_MAX 1600000
#define HID 64
#define SCAN_ELEMS 1024
#define SCAN_MAXB 256

// ---- persistent scratch (no allocation allowed) ----
__device__ int    g_outdeg[N_MAX];
__device__ int    g_indeg[N_MAX];
__device__ int    g_rowptr[N_MAX + 1];
__device__ int    g_cursor[N_MAX];
__device__ int    g_col[E_MAX];
__device__ int    g_part[SCAN_MAXB];
__device__ float  g_nsrc[N_MAX];
__device__ float  g_ndst[N_MAX];
__device__ __half g_hA[N_MAX * HID];   // fp16 storage, fp32 accumulate
__device__ __half g_hB[N_MAX * HID];

// ---------------------------------------------------------------
__global__ void k_init(float* out, int n, int ng) {
    int i = blockIdx.x * blockDim.x + threadIdx.x;
    if (i < n) { g_outdeg[i] = 0; g_indeg[i] = 0; }
    if (i < ng) out[i] = 0.0f;
}

// ---------------------------------------------------------------
// K1: degree counts, 4 edges/thread via int4
// ---------------------------------------------------------------
__global__ void k_deg(const int* __restrict__ src, const int* __restrict__ dst, int e) {
    int i = (blockIdx.x * blockDim.x + threadIdx.x) * 4;
    if (i + 3 < e) {
        int4 s = *(const int4*)&src[i];
        int4 d = *(const int4*)&dst[i];
        atomicAdd(&g_outdeg[s.x], 1); atomicAdd(&g_outdeg[s.y], 1);
        atomicAdd(&g_outdeg[s.z], 1); atomicAdd(&g_outdeg[s.w], 1);
        atomicAdd(&g_indeg[d.x], 1);  atomicAdd(&g_indeg[d.y], 1);
        atomicAdd(&g_indeg[d.z], 1);  atomicAdd(&g_indeg[d.w], 1);
    } else {
        for (; i < e; i++) {
            atomicAdd(&g_outdeg[src[i]], 1);
            atomicAdd(&g_indeg[dst[i]], 1);
        }
    }
}

// ---------------------------------------------------------------
// K2: norms + h0 = emb[feats] * norm_src  -> fp16 rows
// 16 lanes per node, lane owns 4 consecutive cols
// ---------------------------------------------------------------
__global__ void k_embed(const int* __restrict__ feats, const float* __restrict__ emb, int n) {
    int t = blockIdx.x * blockDim.x + threadIdx.x;
    int node = t >> 4;
    int l = t & 15;
    if (node >= n) return;
    float ns = rsqrtf(fmaxf((float)g_outdeg[node], 1.0f));
    if (l == 0) {
        g_nsrc[node] = ns;
        g_ndst[node] = rsqrtf(fmaxf((float)g_indeg[node], 1.0f));
    }
    const float4* e4 = (const float4*)emb;
    float4 v = __ldg(&e4[(long)feats[node] * 16 + l]);
    __half2 r0 = __floats2half2_rn(v.x * ns, v.y * ns);
    __half2 r1 = __floats2half2_rn(v.z * ns, v.w * ns);
    uint2 u;
    u.x = *(unsigned*)&r0; u.y = *(unsigned*)&r1;
    ((uint2*)g_hA)[node * 16 + l] = u;
}

// ---------------------------------------------------------------
// Multi-block exclusive scan of g_indeg -> g_rowptr / g_cursor
// ---------------------------------------------------------------
__global__ void __launch_bounds__(256) k_scan_partial(int n) {
    __shared__ int sred[8];
    int b = blockIdx.x, t = threadIdx.x;
    int base = b * SCAN_ELEMS;
    int s = 0;
    #pragma unroll
    for (int k = 0; k < 4; k++) {
        int i = base + t + k * 256;
        if (i < n) s += g_indeg[i];
    }
    #pragma unroll
    for (int o = 16; o; o >>= 1) s += __shfl_xor_sync(0xffffffffu, s, o);
    if ((t & 31) == 0) sred[t >> 5] = s;
    __syncthreads();
    if (t < 8) {
        int v = sred[t];
        #pragma unroll
        for (int o = 4; o; o >>= 1) v += __shfl_xor_sync(0x000000ffu, v, o);
        if (t == 0) g_part[b] = v;
    }
}

__global__ void __launch_bounds__(256) k_scan_mid(int nb, int n) {
    __shared__ int ws[8];
    int t = threadIdx.x;
    int lane = t & 31, w = t >> 5;
    int v = (t < nb) ? g_part[t] : 0;
    int x = v;
    #pragma unroll
    for (int o = 1; o < 32; o <<= 1) {
        int y = __shfl_up_sync(0xffffffffu, x, o);
        if (lane >= o) x += y;
    }
    if (lane == 31) ws[w] = x;
    __syncthreads();
    if (w == 0) {
        int y = (lane < 8) ? ws[lane] : 0;
        #pragma unroll
        for (int o = 1; o < 8; o <<= 1) {
            int z = __shfl_up_sync(0xffffffffu, y, o);
            if (lane >= o) y += z;
        }
        if (lane < 8) ws[lane] = y;
    }
    __syncthreads();
    int incl = x + (w ? ws[w - 1] : 0);
    if (t < nb) g_part[t] = incl - v;
    if (t == nb - 1) g_rowptr[n] = incl;
}

__global__ void __launch_bounds__(256) k_scan_final(int n) {
    __shared__ int ws[8];
    int b = blockIdx.x, t = threadIdx.x;
    int lane = t & 31, w = t >> 5;
    int idx = b * SCAN_ELEMS + 4 * t;

    int4 d = make_int4(0, 0, 0, 0);
    if (idx + 3 < n) d = *(const int4*)&g_indeg[idx];
    else {
        if (idx + 0 < n) d.x = g_indeg[idx + 0];
        if (idx + 1 < n) d.y = g_indeg[idx + 1];
        if (idx + 2 < n) d.z = g_indeg[idx + 2];
        if (idx + 3 < n) d.w = g_indeg[idx + 3];
    }
    int s0 = d.x, s1 = s0 + d.y, s2 = s1 + d.z, s3 = s2 + d.w;

    int x = s3;
    #pragma unroll
    for (int o = 1; o < 32; o <<= 1) {
        int y = __shfl_up_sync(0xffffffffu, x, o);
        if (lane >= o) x += y;
    }
    if (lane == 31) ws[w] = x;
    __syncthreads();
    if (w == 0) {
        int y = (lane < 8) ? ws[lane] : 0;
        #pragma unroll
        for (int o = 1; o < 8; o <<= 1) {
            int z = __shfl_up_sync(0xffffffffu, y, o);
            if (lane >= o) y += z;
        }
        if (lane < 8) ws[lane] = y;
    }
    __syncthreads();
    int excl = (x - s3) + (w ? ws[w - 1] : 0) + g_part[b];

    int4 r = make_int4(excl, excl + s0, excl + s1, excl + s2);
    if (idx + 3 < n) {
        *(int4*)&g_rowptr[idx] = r;
        *(int4*)&g_cursor[idx] = r;
    } else {
        if (idx + 0 < n) { g_rowptr[idx + 0] = r.x; g_cursor[idx + 0] = r.x; }
        if (idx + 1 < n) { g_rowptr[idx + 1] = r.y; g_cursor[idx + 1] = r.y; }
        if (idx + 2 < n) { g_rowptr[idx + 2] = r.z; g_cursor[idx + 2] = r.z; }
        if (idx + 3 < n) { g_rowptr[idx + 3] = r.w; g_cursor[idx + 3] = r.w; }
    }
}

// ---------------------------------------------------------------
// K4: counting-sort edges by dst into CSR col array, 4 edges/thread
// ---------------------------------------------------------------
__global__ void k_csr(const int* __restrict__ src, const int* __restrict__ dst, int e) {
    int i = (blockIdx.x * blockDim.x + threadIdx.x) * 4;
    if (i + 3 < e) {
        int4 s = *(const int4*)&src[i];
        int4 d = *(const int4*)&dst[i];
        g_col[atomicAdd(&g_cursor[d.x], 1)] = s.x;
        g_col[atomicAdd(&g_cursor[d.y], 1)] = s.y;
        g_col[atomicAdd(&g_cursor[d.z], 1)] = s.z;
        g_col[atomicAdd(&g_cursor[d.w], 1)] = s.w;
    } else {
        for (; i < e; i++)
            g_col[atomicAdd(&g_cursor[dst[i]], 1)] = src[i];
    }
}

// ---------------------------------------------------------------
// K5/K6: fused SpMM (fp16 gather, fp32 accumulate) + dense transform
//        (+ final pooling head). 16 lanes per node, 4 nodes per group.
// ---------------------------------------------------------------
template <bool FINAL>
__global__ void __launch_bounds__(256)
k_spmm(int layer,
       const float* __restrict__ Wg, const float* __restrict__ bg,
       const float* __restrict__ wreg, const int* __restrict__ gid,
       float* __restrict__ out, int n)
{
    __shared__ float sW[HID * HID];
    __shared__ float sb[HID];
    __shared__ float tbuf[16][4][HID];

    const __half* hin  = (layer & 1) ? g_hB : g_hA;
    __half*       hout = (layer & 1) ? g_hA : g_hB;
    const float* W = Wg + (long)layer * HID * HID;
    const float* b = bg + (long)layer * HID;

    int tid = threadIdx.x;
    for (int i = tid; i < HID * HID; i += 256) sW[i] = W[i];
    if (tid < HID) sb[tid] = b[tid];
    __syncthreads();

    int gg = (blockIdx.x * 256 + tid) >> 4;
    int l  = tid & 15;            // lane owns cols 4l..4l+3
    int gl = tid >> 4;
    int base = gg * 4;

    const uint2* hin2 = (const uint2*)hin;   // 4 halfs per lane, 16 per row

    #pragma unroll
    for (int i = 0; i < 4; i++) {
        int node = base + i;
        float4 a = make_float4(0.f, 0.f, 0.f, 0.f);
        if (node < n) {
            int s = g_rowptr[node];
            int e = g_rowptr[node + 1];
            int j = s;
            for (; j + 1 < e; j += 2) {
                int c0 = __ldg(&g_col[j]);
                int c1 = __ldg(&g_col[j + 1]);
                uint2 u0 = __ldg(&hin2[(long)c0 * 16 + l]);
                uint2 u1 = __ldg(&hin2[(long)c1 * 16 + l]);
                float2 f0 = __half22float2(*(__half2*)&u0.x);
                float2 f1 = __half22float2(*(__half2*)&u0.y);
                float2 f2 = __half22float2(*(__half2*)&u1.x);
                float2 f3 = __half22float2(*(__half2*)&u1.y);
                a.x += f0.x + f2.x; a.y += f0.y + f2.y;
                a.z += f1.x + f3.x; a.w += f1.y + f3.y;
            }
            if (j < e) {
                int c0 = __ldg(&g_col[j]);
                uint2 u0 = __ldg(&hin2[(long)c0 * 16 + l]);
                float2 f0 = __half22float2(*(__half2*)&u0.x);
                float2 f1 = __half22float2(*(__half2*)&u0.y);
                a.x += f0.x; a.y += f0.y; a.z += f1.x; a.w += f1.y;
            }
            float nd = g_ndst[node];
            a.x *= nd; a.y *= nd; a.z *= nd; a.w *= nd;
        }
        *(float4*)&tbuf[gl][i][l * 4] = a;
    }
    __syncwarp();

    float4 bb = *(const float4*)&sb[l * 4];
    float4 y0 = bb, y1 = bb, y2 = bb, y3 = bb;
    #pragma unroll 4
    for (int k = 0; k < HID; k++) {
        float4 w = *(const float4*)&sW[k * HID + l * 4];
        float t0 = tbuf[gl][0][k];
        float t1 = tbuf[gl][1][k];
        float t2 = tbuf[gl][2][k];
        float t3 = tbuf[gl][3][k];
        y0.x += t0 * w.x; y0.y += t0 * w.y; y0.z += t0 * w.z; y0.w += t0 * w.w;
        y1.x += t1 * w.x; y1.y += t1 * w.y; y1.z += t1 * w.z; y1.w += t1 * w.w;
        y2.x += t2 * w.x; y2.y += t2 * w.y; y2.z += t2 * w.z; y2.w += t2 * w.w;
        y3.x += t3 * w.x; y3.y += t3 * w.y; y3.z += t3 * w.z; y3.w += t3 * w.w;
    }

    float4 ys[4] = {y0, y1, y2, y3};

    if (!FINAL) {
        #pragma unroll
        for (int i = 0; i < 4; i++) {
            int node = base + i;
            if (node < n) {
                float ns = g_nsrc[node];
                __half2 r0 = __floats2half2_rn(ys[i].x * ns, ys[i].y * ns);
                __half2 r1 = __floats2half2_rn(ys[i].z * ns, ys[i].w * ns);
                uint2 u;
                u.x = *(unsigned*)&r0; u.y = *(unsigned*)&r1;
                ((uint2*)hout)[node * 16 + l] = u;
            }
        }
    } else {
        float4 wr = __ldg((const float4*)wreg + l);
        #pragma unroll
        for (int i = 0; i < 4; i++) {
            int node = base + i;
            float p = 0.0f;
            if (node < n)
                p = ys[i].x * wr.x + ys[i].y * wr.y + ys[i].z * wr.z + ys[i].w * wr.w;
            p += __shfl_xor_sync(0xffffffffu, p, 8);
            p += __shfl_xor_sync(0xffffffffu, p, 4);
            p += __shfl_xor_sync(0xffffffffu, p, 2);
            p += __shfl_xor_sync(0xffffffffu, p, 1);
            if (l == 0 && node < n)
                atomicAdd(&out[gid[node]], p);
        }
    }
}

// ---------------------------------------------------------------
extern "C" void kernel_launch(void* const* d_in, const int* in_sizes, int n_in,
                              void* d_out, int out_size)
{
    const int* feats = (const int*)d_in[0];
    const int* src   = (const int*)d_in[1];
    const int* dst   = (const int*)d_in[2];
    const int* gid   = (const int*)d_in[3];
    int k = 4;
    if (n_in >= 9 && in_sizes[4] == 1) k = 5;
    const float* emb  = (const float*)d_in[k];
    const float* Ws   = (const float*)d_in[k + 1];
    const float* bs   = (const float*)d_in[k + 2];
    const float* wreg = (const float*)d_in[k + 3];
    float* out = (float*)d_out;

    int n = in_sizes[0];
    int e = in_sizes[1];
    int ng = out_size;

    k_init<<<(n + 255) / 256, 256>>>(out, n, ng);
    k_deg<<<(e / 4 + 256) / 256, 256>>>(src, dst, e);
    k_embed<<<(n * 16 + 255) / 256, 256>>>(feats, emb, n);

    int nb = (n + SCAN_ELEMS - 1) / SCAN_ELEMS;
    k_scan_partial<<<nb, 256>>>(n);
    k_scan_mid<<<1, 256>>>(nb, n);
    k_scan_final<<<nb, 256>>>(n);

    k_csr<<<(e / 4 + 256) / 256, 256>>>(src, dst, e);

    int groups = (n + 3) / 4;
    int blocks = (groups + 15) / 16;
    k_spmm<false><<<blocks, 256>>>(0, Ws, bs, wreg, gid, out, n);
    k_spmm<false><<<blocks, 256>>>(1, Ws, bs, wreg, gid, out, n);
    k_spmm<true ><<<blocks, 256>>>(2, Ws, bs, wreg, gid, out, n);
}

// round 4
// speedup vs baseline: 2.0114x; 1.2038x over previous
#include <cuda_runtime.h>
#include <cuda_fp16.h>

#define N_MAX 100000
#define E_MAX 1600000
#define HID 64
#define SCAN_ELEMS 1024
#define SCAN_MAXB 256

// ---- persistent scratch (no allocation allowed) ----
__device__ int    g_outdeg[N_MAX];
__device__ int    g_indeg[N_MAX];
__device__ int    g_rowptr[N_MAX + 1];
__device__ int    g_cursor[N_MAX];
__device__ int    g_col[E_MAX];
__device__ int    g_part[SCAN_MAXB];
__device__ float  g_nsrc[N_MAX];
__device__ float  g_ndst[N_MAX];
__device__ float  g_wfold[HID];     // W2 @ W_reg (folded head)
__device__ float  g_bconst;         // b2 . W_reg
__device__ __half g_hA[N_MAX * HID];
__device__ __half g_hB[N_MAX * HID];

// packed fp32x2 helpers (sm_103a native; ptxas never auto-emits these)
#define FMA2(d, a, b, c) asm("fma.rn.f32x2 %0, %1, %2, %3;" : "=l"(d) : "l"(a), "l"(b), "l"(c))
#define ADD2(d, a, b)    asm("add.rn.f32x2 %0, %1, %2;"     : "=l"(d) : "l"(a), "l"(b))
union F2 { unsigned long long u; float2 f; };

// ---------------------------------------------------------------
__global__ void k_init(float* out, int n, int ng) {
    int i = blockIdx.x * blockDim.x + threadIdx.x;
    if (i < n) { g_outdeg[i] = 0; g_indeg[i] = 0; }
    if (i < ng) out[i] = 0.0f;
}

// fold regression head into layer-2 weights: wfold = W2 . wreg, bconst = b2 . wreg
__global__ void k_fold(const float* __restrict__ Ws, const float* __restrict__ bs,
                       const float* __restrict__ wreg) {
    int k = threadIdx.x;
    const float* W2 = Ws + 2 * HID * HID;
    float s = 0.0f;
    #pragma unroll 8
    for (int o = 0; o < HID; o++) s += W2[k * HID + o] * wreg[o];
    g_wfold[k] = s;
    if (k == 0) {
        float bsum = 0.0f;
        #pragma unroll 8
        for (int o = 0; o < HID; o++) bsum += bs[2 * HID + o] * wreg[o];
        g_bconst = bsum;
    }
}

// ---------------------------------------------------------------
__global__ void k_deg(const int* __restrict__ src, const int* __restrict__ dst, int e) {
    int i = (blockIdx.x * blockDim.x + threadIdx.x) * 4;
    if (i + 3 < e) {
        int4 s = *(const int4*)&src[i];
        int4 d = *(const int4*)&dst[i];
        atomicAdd(&g_outdeg[s.x], 1); atomicAdd(&g_outdeg[s.y], 1);
        atomicAdd(&g_outdeg[s.z], 1); atomicAdd(&g_outdeg[s.w], 1);
        atomicAdd(&g_indeg[d.x], 1);  atomicAdd(&g_indeg[d.y], 1);
        atomicAdd(&g_indeg[d.z], 1);  atomicAdd(&g_indeg[d.w], 1);
    } else {
        for (; i < e; i++) {
            atomicAdd(&g_outdeg[src[i]], 1);
            atomicAdd(&g_indeg[dst[i]], 1);
        }
    }
}

// ---------------------------------------------------------------
__global__ void k_embed(const int* __restrict__ feats, const float* __restrict__ emb, int n) {
    int t = blockIdx.x * blockDim.x + threadIdx.x;
    int node = t >> 4;
    int l = t & 15;
    if (node >= n) return;
    float ns = rsqrtf(fmaxf((float)g_outdeg[node], 1.0f));
    if (l == 0) {
        g_nsrc[node] = ns;
        g_ndst[node] = rsqrtf(fmaxf((float)g_indeg[node], 1.0f));
    }
    const float4* e4 = (const float4*)emb;
    float4 v = __ldg(&e4[(long)feats[node] * 16 + l]);
    __half2 r0 = __floats2half2_rn(v.x * ns, v.y * ns);
    __half2 r1 = __floats2half2_rn(v.z * ns, v.w * ns);
    uint2 u;
    u.x = *(unsigned*)&r0; u.y = *(unsigned*)&r1;
    ((uint2*)g_hA)[node * 16 + l] = u;
}

// ---------------------------------------------------------------
// scan pipeline (unchanged from R2 — measured ~8us total)
// ---------------------------------------------------------------
__global__ void __launch_bounds__(256) k_scan_partial(int n) {
    __shared__ int sred[8];
    int b = blockIdx.x, t = threadIdx.x;
    int base = b * SCAN_ELEMS;
    int s = 0;
    #pragma unroll
    for (int k = 0; k < 4; k++) {
        int i = base + t + k * 256;
        if (i < n) s += g_indeg[i];
    }
    #pragma unroll
    for (int o = 16; o; o >>= 1) s += __shfl_xor_sync(0xffffffffu, s, o);
    if ((t & 31) == 0) sred[t >> 5] = s;
    __syncthreads();
    if (t < 8) {
        int v = sred[t];
        #pragma unroll
        for (int o = 4; o; o >>= 1) v += __shfl_xor_sync(0x000000ffu, v, o);
        if (t == 0) g_part[b] = v;
    }
}

__global__ void __launch_bounds__(256) k_scan_mid(int nb, int n) {
    __shared__ int ws[8];
    int t = threadIdx.x;
    int lane = t & 31, w = t >> 5;
    int v = (t < nb) ? g_part[t] : 0;
    int x = v;
    #pragma unroll
    for (int o = 1; o < 32; o <<= 1) {
        int y = __shfl_up_sync(0xffffffffu, x, o);
        if (lane >= o) x += y;
    }
    if (lane == 31) ws[w] = x;
    __syncthreads();
    if (w == 0) {
        int y = (lane < 8) ? ws[lane] : 0;
        #pragma unroll
        for (int o = 1; o < 8; o <<= 1) {
            int z = __shfl_up_sync(0xffffffffu, y, o);
            if (lane >= o) y += z;
        }
        if (lane < 8) ws[lane] = y;
    }
    __syncthreads();
    int incl = x + (w ? ws[w - 1] : 0);
    if (t < nb) g_part[t] = incl - v;
    if (t == nb - 1) g_rowptr[n] = incl;
}

__global__ void __launch_bounds__(256) k_scan_final(int n) {
    __shared__ int ws[8];
    int b = blockIdx.x, t = threadIdx.x;
    int lane = t & 31, w = t >> 5;
    int idx = b * SCAN_ELEMS + 4 * t;

    int4 d = make_int4(0, 0, 0, 0);
    if (idx + 3 < n) d = *(const int4*)&g_indeg[idx];
    else {
        if (idx + 0 < n) d.x = g_indeg[idx + 0];
        if (idx + 1 < n) d.y = g_indeg[idx + 1];
        if (idx + 2 < n) d.z = g_indeg[idx + 2];
        if (idx + 3 < n) d.w = g_indeg[idx + 3];
    }
    int s0 = d.x, s1 = s0 + d.y, s2 = s1 + d.z, s3 = s2 + d.w;

    int x = s3;
    #pragma unroll
    for (int o = 1; o < 32; o <<= 1) {
        int y = __shfl_up_sync(0xffffffffu, x, o);
        if (lane >= o) x += y;
    }
    if (lane == 31) ws[w] = x;
    __syncthreads();
    if (w == 0) {
        int y = (lane < 8) ? ws[lane] : 0;
        #pragma unroll
        for (int o = 1; o < 8; o <<= 1) {
            int z = __shfl_up_sync(0xffffffffu, y, o);
            if (lane >= o) y += z;
        }
        if (lane < 8) ws[lane] = y;
    }
    __syncthreads();
    int excl = (x - s3) + (w ? ws[w - 1] : 0) + g_part[b];

    int4 r = make_int4(excl, excl + s0, excl + s1, excl + s2);
    if (idx + 3 < n) {
        *(int4*)&g_rowptr[idx] = r;
        *(int4*)&g_cursor[idx] = r;
    } else {
        if (idx + 0 < n) { g_rowptr[idx + 0] = r.x; g_cursor[idx + 0] = r.x; }
        if (idx + 1 < n) { g_rowptr[idx + 1] = r.y; g_cursor[idx + 1] = r.y; }
        if (idx + 2 < n) { g_rowptr[idx + 2] = r.z; g_cursor[idx + 2] = r.z; }
        if (idx + 3 < n) { g_rowptr[idx + 3] = r.w; g_cursor[idx + 3] = r.w; }
    }
}

// ---------------------------------------------------------------
__global__ void k_csr(const int* __restrict__ src, const int* __restrict__ dst, int e) {
    int i = (blockIdx.x * blockDim.x + threadIdx.x) * 4;
    if (i + 3 < e) {
        int4 s = *(const int4*)&src[i];
        int4 d = *(const int4*)&dst[i];
        g_col[atomicAdd(&g_cursor[d.x], 1)] = s.x;
        g_col[atomicAdd(&g_cursor[d.y], 1)] = s.y;
        g_col[atomicAdd(&g_cursor[d.z], 1)] = s.z;
        g_col[atomicAdd(&g_cursor[d.w], 1)] = s.w;
    } else {
        for (; i < e; i++)
            g_col[atomicAdd(&g_cursor[dst[i]], 1)] = src[i];
    }
}

// ---------------------------------------------------------------
// shared gather: 16-lane group, node's aggregated 4 cols (lane-owned),
// 4-edge unroll with packed f32x2 accumulation. Returns dst-normed a01/a23.
// ---------------------------------------------------------------
__device__ __forceinline__ void gather_node(const uint2* __restrict__ hin2,
                                            int node, int l, F2& a01, F2& a23) {
    a01.u = 0ull; a23.u = 0ull;
    int s = g_rowptr[node];
    int e = g_rowptr[node + 1];
    int j = s;
    for (; j + 3 < e; j += 4) {
        int c0 = __ldg(&g_col[j]);
        int c1 = __ldg(&g_col[j + 1]);
        int c2 = __ldg(&g_col[j + 2]);
        int c3 = __ldg(&g_col[j + 3]);
        uint2 u0 = __ldg(&hin2[c0 * 16 + l]);
        uint2 u1 = __ldg(&hin2[c1 * 16 + l]);
        uint2 u2 = __ldg(&hin2[c2 * 16 + l]);
        uint2 u3 = __ldg(&hin2[c3 * 16 + l]);
        F2 t;
        t.f = __half22float2(*(__half2*)&u0.x); ADD2(a01.u, a01.u, t.u);
        t.f = __half22float2(*(__half2*)&u0.y); ADD2(a23.u, a23.u, t.u);
        t.f = __half22float2(*(__half2*)&u1.x); ADD2(a01.u, a01.u, t.u);
        t.f = __half22float2(*(__half2*)&u1.y); ADD2(a23.u, a23.u, t.u);
        t.f = __half22float2(*(__half2*)&u2.x); ADD2(a01.u, a01.u, t.u);
        t.f = __half22float2(*(__half2*)&u2.y); ADD2(a23.u, a23.u, t.u);
        t.f = __half22float2(*(__half2*)&u3.x); ADD2(a01.u, a01.u, t.u);
        t.f = __half22float2(*(__half2*)&u3.y); ADD2(a23.u, a23.u, t.u);
    }
    for (; j < e; j++) {
        int c0 = __ldg(&g_col[j]);
        uint2 u0 = __ldg(&hin2[c0 * 16 + l]);
        F2 t;
        t.f = __half22float2(*(__half2*)&u0.x); ADD2(a01.u, a01.u, t.u);
        t.f = __half22float2(*(__half2*)&u0.y); ADD2(a23.u, a23.u, t.u);
    }
    float nd = g_ndst[node];
    a01.f.x *= nd; a01.f.y *= nd; a23.f.x *= nd; a23.f.y *= nd;
}

// ---------------------------------------------------------------
// layers 0/1: gather + transform (f32x2, dup-tbuf) + prescaled fp16 write
// smem: sW 16KB + tbuf 32KB = 49152B exactly
// ---------------------------------------------------------------
__global__ void __launch_bounds__(256)
k_spmm(int layer, const float* __restrict__ Wg, const float* __restrict__ bg, int n)
{
    __shared__ __align__(16) float  sW[HID * HID];
    __shared__ __align__(16) float2 tbuf[16][4][HID];   // (t,t) duplicated

    const __half* hin  = (layer & 1) ? g_hB : g_hA;
    __half*       hout = (layer & 1) ? g_hA : g_hB;
    const float* W = Wg + layer * HID * HID;
    const float* b = bg + layer * HID;

    int tid = threadIdx.x;
    for (int i = tid; i < HID * HID; i += 256) sW[i] = W[i];
    __syncthreads();

    int gg = (blockIdx.x * 256 + tid) >> 4;
    int l  = tid & 15;
    int gl = tid >> 4;
    int base = gg * 4;

    const uint2* hin2 = (const uint2*)hin;

    #pragma unroll
    for (int i = 0; i < 4; i++) {
        int node = base + i;
        F2 a01, a23; a01.u = 0ull; a23.u = 0ull;
        if (node < n) gather_node(hin2, node, l, a01, a23);
        float4* tp = (float4*)&tbuf[gl][i][l * 4];
        tp[0] = make_float4(a01.f.x, a01.f.x, a01.f.y, a01.f.y);
        tp[1] = make_float4(a23.f.x, a23.f.x, a23.f.y, a23.f.y);
    }
    __syncwarp();

    // y = t @ W + b  via packed f32x2 FMAs
    float4 bb = __ldg((const float4*)&b[l * 4]);
    F2 yab[4], ycd[4];
    #pragma unroll
    for (int i = 0; i < 4; i++) {
        yab[i].f = make_float2(bb.x, bb.y);
        ycd[i].f = make_float2(bb.z, bb.w);
    }
    #pragma unroll 4
    for (int k = 0; k < HID; k++) {
        float4 w = *(const float4*)&sW[k * HID + l * 4];
        unsigned long long wab = ((const unsigned long long*)&w)[0];
        unsigned long long wcd = ((const unsigned long long*)&w)[1];
        #pragma unroll
        for (int i = 0; i < 4; i++) {
            unsigned long long tp = *(const unsigned long long*)&tbuf[gl][i][k];
            FMA2(yab[i].u, tp, wab, yab[i].u);
            FMA2(ycd[i].u, tp, wcd, ycd[i].u);
        }
    }

    #pragma unroll
    for (int i = 0; i < 4; i++) {
        int node = base + i;
        if (node < n) {
            float ns = g_nsrc[node];
            __half2 r0 = __floats2half2_rn(yab[i].f.x * ns, yab[i].f.y * ns);
            __half2 r1 = __floats2half2_rn(ycd[i].f.x * ns, ycd[i].f.y * ns);
            uint2 u;
            u.x = *(unsigned*)&r0; u.y = *(unsigned*)&r1;
            ((uint2*)hout)[node * 16 + l] = u;
        }
    }
}

// ---------------------------------------------------------------
// final layer: gather + folded-head dot + pooled atomic (no transform)
// ---------------------------------------------------------------
__global__ void __launch_bounds__(256)
k_final(const int* __restrict__ gid, float* __restrict__ out, int n)
{
    int tid = threadIdx.x;
    int gg = (blockIdx.x * 256 + tid) >> 4;
    int l  = tid & 15;
    int base = gg * 4;

    const uint2* hin2 = (const uint2*)g_hA;   // layer1 output lives in hA
    float4 wf = __ldg((const float4*)&g_wfold[l * 4]);
    float bconst = g_bconst;

    #pragma unroll
    for (int i = 0; i < 4; i++) {
        int node = base + i;
        float p = 0.0f;
        if (node < n) {
            F2 a01, a23;
            gather_node(hin2, node, l, a01, a23);
            p = a01.f.x * wf.x + a01.f.y * wf.y + a23.f.x * wf.z + a23.f.y * wf.w;
        }
        p += __shfl_xor_sync(0xffffffffu, p, 8);
        p += __shfl_xor_sync(0xffffffffu, p, 4);
        p += __shfl_xor_sync(0xffffffffu, p, 2);
        p += __shfl_xor_sync(0xffffffffu, p, 1);
        if (l == 0 && node < n)
            atomicAdd(&out[gid[node]], p + bconst);
    }
}

// ---------------------------------------------------------------
extern "C" void kernel_launch(void* const* d_in, const int* in_sizes, int n_in,
                              void* d_out, int out_size)
{
    const int* feats = (const int*)d_in[0];
    const int* src   = (const int*)d_in[1];
    const int* dst   = (const int*)d_in[2];
    const int* gid   = (const int*)d_in[3];
    int k = 4;
    if (n_in >= 9 && in_sizes[4] == 1) k = 5;
    const float* emb  = (const float*)d_in[k];
    const float* Ws   = (const float*)d_in[k + 1];
    const float* bs   = (const float*)d_in[k + 2];
    const float* wreg = (const float*)d_in[k + 3];
    float* out = (float*)d_out;

    int n = in_sizes[0];
    int e = in_sizes[1];
    int ng = out_size;

    k_fold<<<1, HID>>>(Ws, bs, wreg);
    k_init<<<(n + 255) / 256, 256>>>(out, n, ng);
    k_deg<<<(e / 4 + 256) / 256, 256>>>(src, dst, e);
    k_embed<<<(n * 16 + 255) / 256, 256>>>(feats, emb, n);

    int nb = (n + SCAN_ELEMS - 1) / SCAN_ELEMS;
    k_scan_partial<<<nb, 256>>>(n);
    k_scan_mid<<<1, 256>>>(nb, n);
    k_scan_final<<<nb, 256>>>(n);

    k_csr<<<(e / 4 + 256) / 256, 256>>>(src, dst, e);

    int groups = (n + 3) / 4;
    int blocks = (groups + 15) / 16;
    k_spmm<<<blocks, 256>>>(0, Ws, bs, n);
    k_spmm<<<blocks, 256>>>(1, Ws, bs, n);
    k_final<<<blocks, 256>>>(gid, out, n);
}

// round 5
// speedup vs baseline: 2.0120x; 1.0003x over previous
#include <cuda_runtime.h>
#include <cuda_fp16.h>

#define N_MAX 100000
#define E_MAX 1600000
#define HID 64
#define SCAN_ELEMS 1024
#define SCAN_MAXB 256

// ---- persistent scratch (no allocation allowed) ----
__device__ int    g_outdeg[N_MAX];
__device__ int    g_indeg[N_MAX];
__device__ int    g_rowptr[N_MAX + 1];
__device__ int    g_cursor[N_MAX];
__device__ int    g_col[E_MAX];
__device__ int    g_part[SCAN_MAXB];
__device__ float  g_nsrc[N_MAX];
__device__ float  g_ndst[N_MAX];
__device__ float  g_wfold[HID];     // W2 @ W_reg (folded head)
__device__ float  g_bconst;         // b2 . W_reg
__device__ float  g_q[N_MAX];       // per-node scalar for final layer
__device__ __half g_hA[N_MAX * HID];
__device__ __half g_hB[N_MAX * HID];

// packed fp32x2 helpers
#define FMA2(d, a, b, c) asm("fma.rn.f32x2 %0, %1, %2, %3;" : "=l"(d) : "l"(a), "l"(b), "l"(c))
#define ADD2(d, a, b)    asm("add.rn.f32x2 %0, %1, %2;"     : "=l"(d) : "l"(a), "l"(b))
union F2 { unsigned long long u; float2 f; };

// ---------------------------------------------------------------
__global__ void k_init(float* out, int n, int ng) {
    int i = blockIdx.x * blockDim.x + threadIdx.x;
    if (i < n) { g_outdeg[i] = 0; g_indeg[i] = 0; }
    if (i < ng) out[i] = 0.0f;
}

// fold regression head into layer-2 weights
__global__ void k_fold(const float* __restrict__ Ws, const float* __restrict__ bs,
                       const float* __restrict__ wreg) {
    int k = threadIdx.x;
    const float* W2 = Ws + 2 * HID * HID;
    float s = 0.0f;
    #pragma unroll 8
    for (int o = 0; o < HID; o++) s += W2[k * HID + o] * wreg[o];
    g_wfold[k] = s;
    if (k == 0) {
        float bsum = 0.0f;
        #pragma unroll 8
        for (int o = 0; o < HID; o++) bsum += bs[2 * HID + o] * wreg[o];
        g_bconst = bsum;
    }
}

// ---------------------------------------------------------------
__global__ void k_deg(const int* __restrict__ src, const int* __restrict__ dst, int e) {
    int i = (blockIdx.x * blockDim.x + threadIdx.x) * 4;
    if (i + 3 < e) {
        int4 s = *(const int4*)&src[i];
        int4 d = *(const int4*)&dst[i];
        atomicAdd(&g_outdeg[s.x], 1); atomicAdd(&g_outdeg[s.y], 1);
        atomicAdd(&g_outdeg[s.z], 1); atomicAdd(&g_outdeg[s.w], 1);
        atomicAdd(&g_indeg[d.x], 1);  atomicAdd(&g_indeg[d.y], 1);
        atomicAdd(&g_indeg[d.z], 1);  atomicAdd(&g_indeg[d.w], 1);
    } else {
        for (; i < e; i++) {
            atomicAdd(&g_outdeg[src[i]], 1);
            atomicAdd(&g_indeg[dst[i]], 1);
        }
    }
}

// ---------------------------------------------------------------
__global__ void k_embed(const int* __restrict__ feats, const float* __restrict__ emb, int n) {
    int t = blockIdx.x * blockDim.x + threadIdx.x;
    int node = t >> 4;
    int l = t & 15;
    if (node >= n) return;
    float ns = rsqrtf(fmaxf((float)g_outdeg[node], 1.0f));
    if (l == 0) {
        g_nsrc[node] = ns;
        g_ndst[node] = rsqrtf(fmaxf((float)g_indeg[node], 1.0f));
    }
    const float4* e4 = (const float4*)emb;
    float4 v = __ldg(&e4[(long)feats[node] * 16 + l]);
    __half2 r0 = __floats2half2_rn(v.x * ns, v.y * ns);
    __half2 r1 = __floats2half2_rn(v.z * ns, v.w * ns);
    uint2 u;
    u.x = *(unsigned*)&r0; u.y = *(unsigned*)&r1;
    ((uint2*)g_hA)[node * 16 + l] = u;
}

// ---------------------------------------------------------------
// scan pipeline (unchanged — measured ~8us total)
// ---------------------------------------------------------------
__global__ void __launch_bounds__(256) k_scan_partial(int n) {
    __shared__ int sred[8];
    int b = blockIdx.x, t = threadIdx.x;
    int base = b * SCAN_ELEMS;
    int s = 0;
    #pragma unroll
    for (int k = 0; k < 4; k++) {
        int i = base + t + k * 256;
        if (i < n) s += g_indeg[i];
    }
    #pragma unroll
    for (int o = 16; o; o >>= 1) s += __shfl_xor_sync(0xffffffffu, s, o);
    if ((t & 31) == 0) sred[t >> 5] = s;
    __syncthreads();
    if (t < 8) {
        int v = sred[t];
        #pragma unroll
        for (int o = 4; o; o >>= 1) v += __shfl_xor_sync(0x000000ffu, v, o);
        if (t == 0) g_part[b] = v;
    }
}

__global__ void __launch_bounds__(256) k_scan_mid(int nb, int n) {
    __shared__ int ws[8];
    int t = threadIdx.x;
    int lane = t & 31, w = t >> 5;
    int v = (t < nb) ? g_part[t] : 0;
    int x = v;
    #pragma unroll
    for (int o = 1; o < 32; o <<= 1) {
        int y = __shfl_up_sync(0xffffffffu, x, o);
        if (lane >= o) x += y;
    }
    if (lane == 31) ws[w] = x;
    __syncthreads();
    if (w == 0) {
        int y = (lane < 8) ? ws[lane] : 0;
        #pragma unroll
        for (int o = 1; o < 8; o <<= 1) {
            int z = __shfl_up_sync(0xffffffffu, y, o);
            if (lane >= o) y += z;
        }
        if (lane < 8) ws[lane] = y;
    }
    __syncthreads();
    int incl = x + (w ? ws[w - 1] : 0);
    if (t < nb) g_part[t] = incl - v;
    if (t == nb - 1) g_rowptr[n] = incl;
}

__global__ void __launch_bounds__(256) k_scan_final(int n) {
    __shared__ int ws[8];
    int b = blockIdx.x, t = threadIdx.x;
    int lane = t & 31, w = t >> 5;
    int idx = b * SCAN_ELEMS + 4 * t;

    int4 d = make_int4(0, 0, 0, 0);
    if (idx + 3 < n) d = *(const int4*)&g_indeg[idx];
    else {
        if (idx + 0 < n) d.x = g_indeg[idx + 0];
        if (idx + 1 < n) d.y = g_indeg[idx + 1];
        if (idx + 2 < n) d.z = g_indeg[idx + 2];
        if (idx + 3 < n) d.w = g_indeg[idx + 3];
    }
    int s0 = d.x, s1 = s0 + d.y, s2 = s1 + d.z, s3 = s2 + d.w;

    int x = s3;
    #pragma unroll
    for (int o = 1; o < 32; o <<= 1) {
        int y = __shfl_up_sync(0xffffffffu, x, o);
        if (lane >= o) x += y;
    }
    if (lane == 31) ws[w] = x;
    __syncthreads();
    if (w == 0) {
        int y = (lane < 8) ? ws[lane] : 0;
        #pragma unroll
        for (int o = 1; o < 8; o <<= 1) {
            int z = __shfl_up_sync(0xffffffffu, y, o);
            if (lane >= o) y += z;
        }
        if (lane < 8) ws[lane] = y;
    }
    __syncthreads();
    int excl = (x - s3) + (w ? ws[w - 1] : 0) + g_part[b];

    int4 r = make_int4(excl, excl + s0, excl + s1, excl + s2);
    if (idx + 3 < n) {
        *(int4*)&g_rowptr[idx] = r;
        *(int4*)&g_cursor[idx] = r;
    } else {
        if (idx + 0 < n) { g_rowptr[idx + 0] = r.x; g_cursor[idx + 0] = r.x; }
        if (idx + 1 < n) { g_rowptr[idx + 1] = r.y; g_cursor[idx + 1] = r.y; }
        if (idx + 2 < n) { g_rowptr[idx + 2] = r.z; g_cursor[idx + 2] = r.z; }
        if (idx + 3 < n) { g_rowptr[idx + 3] = r.w; g_cursor[idx + 3] = r.w; }
    }
}

// ---------------------------------------------------------------
__global__ void k_csr(const int* __restrict__ src, const int* __restrict__ dst, int e) {
    int i = (blockIdx.x * blockDim.x + threadIdx.x) * 4;
    if (i + 3 < e) {
        int4 s = *(const int4*)&src[i];
        int4 d = *(const int4*)&dst[i];
        g_col[atomicAdd(&g_cursor[d.x], 1)] = s.x;
        g_col[atomicAdd(&g_cursor[d.y], 1)] = s.y;
        g_col[atomicAdd(&g_cursor[d.z], 1)] = s.z;
        g_col[atomicAdd(&g_cursor[d.w], 1)] = s.w;
    } else {
        for (; i < e; i++)
            g_col[atomicAdd(&g_cursor[dst[i]], 1)] = src[i];
    }
}

// ---------------------------------------------------------------
// vector gather: 16-lane group, dual accumulators break the add chain
// ---------------------------------------------------------------
__device__ __forceinline__ void gather_node(const uint2* __restrict__ hin2,
                                            int node, int l, F2& a01, F2& a23) {
    F2 b01, b23;
    a01.u = 0ull; a23.u = 0ull; b01.u = 0ull; b23.u = 0ull;
    int s = g_rowptr[node];
    int e = g_rowptr[node + 1];
    int j = s;
    for (; j + 3 < e; j += 4) {
        int c0 = __ldg(&g_col[j]);
        int c1 = __ldg(&g_col[j + 1]);
        int c2 = __ldg(&g_col[j + 2]);
        int c3 = __ldg(&g_col[j + 3]);
        uint2 u0 = __ldg(&hin2[c0 * 16 + l]);
        uint2 u1 = __ldg(&hin2[c1 * 16 + l]);
        uint2 u2 = __ldg(&hin2[c2 * 16 + l]);
        uint2 u3 = __ldg(&hin2[c3 * 16 + l]);
        F2 t;
        t.f = __half22float2(*(__half2*)&u0.x); ADD2(a01.u, a01.u, t.u);
        t.f = __half22float2(*(__half2*)&u0.y); ADD2(a23.u, a23.u, t.u);
        t.f = __half22float2(*(__half2*)&u1.x); ADD2(b01.u, b01.u, t.u);
        t.f = __half22float2(*(__half2*)&u1.y); ADD2(b23.u, b23.u, t.u);
        t.f = __half22float2(*(__half2*)&u2.x); ADD2(a01.u, a01.u, t.u);
        t.f = __half22float2(*(__half2*)&u2.y); ADD2(a23.u, a23.u, t.u);
        t.f = __half22float2(*(__half2*)&u3.x); ADD2(b01.u, b01.u, t.u);
        t.f = __half22float2(*(__half2*)&u3.y); ADD2(b23.u, b23.u, t.u);
    }
    for (; j < e; j++) {
        int c0 = __ldg(&g_col[j]);
        uint2 u0 = __ldg(&hin2[c0 * 16 + l]);
        F2 t;
        t.f = __half22float2(*(__half2*)&u0.x); ADD2(a01.u, a01.u, t.u);
        t.f = __half22float2(*(__half2*)&u0.y); ADD2(a23.u, a23.u, t.u);
    }
    ADD2(a01.u, a01.u, b01.u);
    ADD2(a23.u, a23.u, b23.u);
    float nd = g_ndst[node];
    a01.f.x *= nd; a01.f.y *= nd; a23.f.x *= nd; a23.f.y *= nd;
}

// ---------------------------------------------------------------
// layers 0/1: gather + f32x2 transform + prescaled fp16 write
// ---------------------------------------------------------------
__global__ void __launch_bounds__(256)
k_spmm(int layer, const float* __restrict__ Wg, const float* __restrict__ bg, int n)
{
    __shared__ __align__(16) float  sW[HID * HID];
    __shared__ __align__(16) float2 tbuf[16][4][HID];

    const __half* hin  = (layer & 1) ? g_hB : g_hA;
    __half*       hout = (layer & 1) ? g_hA : g_hB;
    const float* W = Wg + layer * HID * HID;
    const float* b = bg + layer * HID;

    int tid = threadIdx.x;
    for (int i = tid; i < HID * HID; i += 256) sW[i] = W[i];
    __syncthreads();

    int gg = (blockIdx.x * 256 + tid) >> 4;
    int l  = tid & 15;
    int gl = tid >> 4;
    int base = gg * 4;

    const uint2* hin2 = (const uint2*)hin;

    #pragma unroll
    for (int i = 0; i < 4; i++) {
        int node = base + i;
        F2 a01, a23; a01.u = 0ull; a23.u = 0ull;
        if (node < n) gather_node(hin2, node, l, a01, a23);
        float4* tp = (float4*)&tbuf[gl][i][l * 4];
        tp[0] = make_float4(a01.f.x, a01.f.x, a01.f.y, a01.f.y);
        tp[1] = make_float4(a23.f.x, a23.f.x, a23.f.y, a23.f.y);
    }
    __syncwarp();

    float4 bb = __ldg((const float4*)&b[l * 4]);
    F2 yab[4], ycd[4];
    #pragma unroll
    for (int i = 0; i < 4; i++) {
        yab[i].f = make_float2(bb.x, bb.y);
        ycd[i].f = make_float2(bb.z, bb.w);
    }
    #pragma unroll 4
    for (int k = 0; k < HID; k++) {
        float4 w = *(const float4*)&sW[k * HID + l * 4];
        unsigned long long wab = ((const unsigned long long*)&w)[0];
        unsigned long long wcd = ((const unsigned long long*)&w)[1];
        #pragma unroll
        for (int i = 0; i < 4; i++) {
            unsigned long long tp = *(const unsigned long long*)&tbuf[gl][i][k];
            FMA2(yab[i].u, tp, wab, yab[i].u);
            FMA2(ycd[i].u, tp, wcd, ycd[i].u);
        }
    }

    #pragma unroll
    for (int i = 0; i < 4; i++) {
        int node = base + i;
        if (node < n) {
            float ns = g_nsrc[node];
            __half2 r0 = __floats2half2_rn(yab[i].f.x * ns, yab[i].f.y * ns);
            __half2 r1 = __floats2half2_rn(ycd[i].f.x * ns, ycd[i].f.y * ns);
            uint2 u;
            u.x = *(unsigned*)&r0; u.y = *(unsigned*)&r1;
            ((uint2*)hout)[node * 16 + l] = u;
        }
    }
}

// ---------------------------------------------------------------
// k_q: per-node scalar q[n] = h1_prescaled[n] . wfold   (16 lanes/node)
// ---------------------------------------------------------------
__global__ void __launch_bounds__(256)
k_q(int n)
{
    int t = blockIdx.x * blockDim.x + threadIdx.x;
    int node = t >> 4;
    int l = t & 15;
    if (node >= n) return;
    const uint2* h2 = (const uint2*)g_hA;      // layer-1 output (prescaled by nsrc)
    uint2 u = __ldg(&h2[node * 16 + l]);
    float2 f0 = __half22float2(*(__half2*)&u.x);
    float2 f1 = __half22float2(*(__half2*)&u.y);
    float4 wf = __ldg((const float4*)&g_wfold[l * 4]);
    float p = f0.x * wf.x + f0.y * wf.y + f1.x * wf.z + f1.y * wf.w;
    p += __shfl_xor_sync(0xffffffffu, p, 8);
    p += __shfl_xor_sync(0xffffffffu, p, 4);
    p += __shfl_xor_sync(0xffffffffu, p, 2);
    p += __shfl_xor_sync(0xffffffffu, p, 1);
    if (l == 0) g_q[node] = p;
}

// ---------------------------------------------------------------
// final layer via scalars: 4 lanes per node sum q[col], pooled atomic
// ---------------------------------------------------------------
__global__ void __launch_bounds__(256)
k_final(const int* __restrict__ gid, float* __restrict__ out, int n)
{
    int t = blockIdx.x * blockDim.x + threadIdx.x;
    int node = t >> 2;
    int l = t & 3;
    if (node >= n) return;

    int s = g_rowptr[node];
    int e = g_rowptr[node + 1];
    float sA = 0.0f, sB = 0.0f;
    int j = s + l;
    for (; j + 4 < e; j += 8) {
        int c0 = __ldg(&g_col[j]);
        int c1 = __ldg(&g_col[j + 4]);
        sA += __ldg(&g_q[c0]);
        sB += __ldg(&g_q[c1]);
    }
    if (j < e) sA += __ldg(&g_q[__ldg(&g_col[j])]);
    float p = sA + sB;
    p += __shfl_xor_sync(0xffffffffu, p, 2);
    p += __shfl_xor_sync(0xffffffffu, p, 1);
    if (l == 0)
        atomicAdd(&out[gid[node]], p * g_ndst[node] + g_bconst);
}

// ---------------------------------------------------------------
extern "C" void kernel_launch(void* const* d_in, const int* in_sizes, int n_in,
                              void* d_out, int out_size)
{
    const int* feats = (const int*)d_in[0];
    const int* src   = (const int*)d_in[1];
    const int* dst   = (const int*)d_in[2];
    const int* gid   = (const int*)d_in[3];
    int k = 4;
    if (n_in >= 9 && in_sizes[4] == 1) k = 5;
    const float* emb  = (const float*)d_in[k];
    const float* Ws   = (const float*)d_in[k + 1];
    const float* bs   = (const float*)d_in[k + 2];
    const float* wreg = (const float*)d_in[k + 3];
    float* out = (float*)d_out;

    int n = in_sizes[0];
    int e = in_sizes[1];
    int ng = out_size;

    k_fold<<<1, HID>>>(Ws, bs, wreg);
    k_init<<<(n + 255) / 256, 256>>>(out, n, ng);
    k_deg<<<(e / 4 + 256) / 256, 256>>>(src, dst, e);
    k_embed<<<(n * 16 + 255) / 256, 256>>>(feats, emb, n);

    int nb = (n + SCAN_ELEMS - 1) / SCAN_ELEMS;
    k_scan_partial<<<nb, 256>>>(n);
    k_scan_mid<<<1, 256>>>(nb, n);
    k_scan_final<<<nb, 256>>>(n);

    k_csr<<<(e / 4 + 256) / 256, 256>>>(src, dst, e);

    int groups = (n + 3) / 4;
    int blocks = (groups + 15) / 16;
    k_spmm<<<blocks, 256>>>(0, Ws, bs, n);
    k_spmm<<<blocks, 256>>>(1, Ws, bs, n);
    k_q<<<(n * 16 + 255) / 256, 256>>>(n);
    k_final<<<(n * 4 + 255) / 256, 256>>>(gid, out, n);
}

// round 6
// speedup vs baseline: 3.3640x; 1.6719x over previous
#include <cuda_runtime.h>

#define N_MAX 100000
#define HID 64
#define V_MAX 16384

// ---- persistent scratch (no allocation allowed) ----
__device__ int    g_outdeg[N_MAX];
__device__ int    g_indeg[N_MAX];
__device__ float  g_nsrc[N_MAX];
__device__ float  g_ndst[N_MAX];
__device__ float  g_v[HID];        // W0 W1 W2 wreg
__device__ float  g_c0, g_c1, g_c2;
__device__ float  g_tdot[V_MAX];   // emb_table . v  (per vocab word)
__device__ float2 g_P[N_MAX];      // prescaled (value, ones) pair
__device__ float2 g_A[N_MAX];      // float2 accumulator
__device__ float  g_Ps[N_MAX];     // prescaled scalar (last prop)
__device__ float  g_As[N_MAX];     // scalar accumulator
__device__ float  g_s1[N_MAX];     // S^1 1
__device__ float  g_s2[N_MAX];     // S^2 1

// ---------------------------------------------------------------
// K0: zero degrees, accumulators, output
// ---------------------------------------------------------------
__global__ void k_init(float* out, int n, int ng) {
    int i = blockIdx.x * blockDim.x + threadIdx.x;
    if (i < n) {
        g_outdeg[i] = 0; g_indeg[i] = 0;
        g_A[i] = make_float2(0.f, 0.f);
        g_As[i] = 0.f;
    }
    if (i < ng) out[i] = 0.0f;
}

// ---------------------------------------------------------------
// K1: fold all weights into v and the bias scalars c0,c1,c2
//   a = W2.wreg ; b = W1.a ; v = W0.b
//   c2 = b2.wreg ; c1 = b1.a ; c0 = b0.b
// ---------------------------------------------------------------
__global__ void k_fold(const float* __restrict__ Ws, const float* __restrict__ bs,
                       const float* __restrict__ wreg) {
    __shared__ float sa[HID], sb[HID];
    int k = threadIdx.x;
    float s = 0.f;
    #pragma unroll 8
    for (int j = 0; j < HID; j++) s += Ws[2 * HID * HID + k * HID + j] * wreg[j];
    sa[k] = s;
    __syncthreads();
    s = 0.f;
    #pragma unroll 8
    for (int j = 0; j < HID; j++) s += Ws[1 * HID * HID + k * HID + j] * sa[j];
    sb[k] = s;
    __syncthreads();
    s = 0.f;
    #pragma unroll 8
    for (int j = 0; j < HID; j++) s += Ws[0 * HID * HID + k * HID + j] * sb[j];
    g_v[k] = s;
    if (k == 0) {
        float c2 = 0.f, c1 = 0.f, c0 = 0.f;
        #pragma unroll 8
        for (int j = 0; j < HID; j++) {
            c2 += bs[2 * HID + j] * wreg[j];
            c1 += bs[1 * HID + j] * sa[j];
            c0 += bs[0 * HID + j] * sb[j];
        }
        g_c2 = c2; g_c1 = c1; g_c0 = c0;
    }
}

// ---------------------------------------------------------------
// K2: degree counts, 4 edges/thread
// ---------------------------------------------------------------
__global__ void k_deg(const int* __restrict__ src, const int* __restrict__ dst, int e) {
    int i = (blockIdx.x * blockDim.x + threadIdx.x) * 4;
    if (i + 3 < e) {
        int4 s = *(const int4*)&src[i];
        int4 d = *(const int4*)&dst[i];
        atomicAdd(&g_outdeg[s.x], 1); atomicAdd(&g_outdeg[s.y], 1);
        atomicAdd(&g_outdeg[s.z], 1); atomicAdd(&g_outdeg[s.w], 1);
        atomicAdd(&g_indeg[d.x], 1);  atomicAdd(&g_indeg[d.y], 1);
        atomicAdd(&g_indeg[d.z], 1);  atomicAdd(&g_indeg[d.w], 1);
    } else {
        for (; i < e; i++) {
            atomicAdd(&g_outdeg[src[i]], 1);
            atomicAdd(&g_indeg[dst[i]], 1);
        }
    }
}

// ---------------------------------------------------------------
// K3: tdot[w] = emb[w] . v   (16 lanes per vocab word)
// ---------------------------------------------------------------
__global__ void k_tdot(const float* __restrict__ emb, int vocab) {
    int t = blockIdx.x * blockDim.x + threadIdx.x;
    int w = t >> 4;
    int l = t & 15;
    if (w >= vocab) return;
    float4 ev = __ldg((const float4*)emb + w * 16 + l);
    float4 vv = *(const float4*)&g_v[l * 4];
    float p = ev.x * vv.x + ev.y * vv.y + ev.z * vv.z + ev.w * vv.w;
    p += __shfl_xor_sync(0xffffffffu, p, 8);
    p += __shfl_xor_sync(0xffffffffu, p, 4);
    p += __shfl_xor_sync(0xffffffffu, p, 2);
    p += __shfl_xor_sync(0xffffffffu, p, 1);
    if (l == 0) g_tdot[w] = p;
}

// ---------------------------------------------------------------
// K4: norms + initial prescaled pair P0 = (z0, 1) * nsrc
// ---------------------------------------------------------------
__global__ void k_p0(const int* __restrict__ feats, int n) {
    int i = blockIdx.x * blockDim.x + threadIdx.x;
    if (i >= n) return;
    float ns = rsqrtf(fmaxf((float)g_outdeg[i], 1.0f));
    float nd = rsqrtf(fmaxf((float)g_indeg[i], 1.0f));
    g_nsrc[i] = ns;
    g_ndst[i] = nd;
    float z0 = __ldg(&g_tdot[feats[i]]);
    g_P[i] = make_float2(z0 * ns, ns);
}

// ---------------------------------------------------------------
// K5: float2 scatter propagation: A[dst] += P[src]  (4 edges/thread)
// ---------------------------------------------------------------
__global__ void k_prop2(const int* __restrict__ src, const int* __restrict__ dst, int e) {
    int i = (blockIdx.x * blockDim.x + threadIdx.x) * 4;
    if (i + 3 < e) {
        int4 s = *(const int4*)&src[i];
        int4 d = *(const int4*)&dst[i];
        float2 p0 = __ldg(&g_P[s.x]);
        float2 p1 = __ldg(&g_P[s.y]);
        float2 p2 = __ldg(&g_P[s.z]);
        float2 p3 = __ldg(&g_P[s.w]);
        atomicAdd(&g_A[d.x].x, p0.x); atomicAdd(&g_A[d.x].y, p0.y);
        atomicAdd(&g_A[d.y].x, p1.x); atomicAdd(&g_A[d.y].y, p1.y);
        atomicAdd(&g_A[d.z].x, p2.x); atomicAdd(&g_A[d.z].y, p2.y);
        atomicAdd(&g_A[d.w].x, p3.x); atomicAdd(&g_A[d.w].y, p3.y);
    } else {
        for (; i < e; i++) {
            float2 p = __ldg(&g_P[src[i]]);
            atomicAdd(&g_A[dst[i]].x, p.x);
            atomicAdd(&g_A[dst[i]].y, p.y);
        }
    }
}

// ---------------------------------------------------------------
// K6: rescale after prop1: U1 = A*ndst; s1 = U1.y; P = U1*nsrc; A = 0
// ---------------------------------------------------------------
__global__ void k_rescale1(int n) {
    int i = blockIdx.x * blockDim.x + threadIdx.x;
    if (i >= n) return;
    float2 A = g_A[i];
    float nd = g_ndst[i], ns = g_nsrc[i];
    float u = A.x * nd, ss = A.y * nd;
    g_s1[i] = ss;
    g_P[i] = make_float2(u * ns, ss * ns);
    g_A[i] = make_float2(0.f, 0.f);
}

// ---------------------------------------------------------------
// K7: rescale after prop2: U2 = A*ndst; s2 = U2.y; Ps = U2.x*nsrc
// ---------------------------------------------------------------
__global__ void k_rescale2(int n) {
    int i = blockIdx.x * blockDim.x + threadIdx.x;
    if (i >= n) return;
    float2 A = g_A[i];
    float nd = g_ndst[i], ns = g_nsrc[i];
    float u = A.x * nd, ss = A.y * nd;
    g_s2[i] = ss;
    g_Ps[i] = u * ns;
}

// ---------------------------------------------------------------
// K8: scalar scatter propagation: As[dst] += Ps[src]
// ---------------------------------------------------------------
__global__ void k_prop1(const int* __restrict__ src, const int* __restrict__ dst, int e) {
    int i = (blockIdx.x * blockDim.x + threadIdx.x) * 4;
    if (i + 3 < e) {
        int4 s = *(const int4*)&src[i];
        int4 d = *(const int4*)&dst[i];
        float p0 = __ldg(&g_Ps[s.x]);
        float p1 = __ldg(&g_Ps[s.y]);
        float p2 = __ldg(&g_Ps[s.z]);
        float p3 = __ldg(&g_Ps[s.w]);
        atomicAdd(&g_As[d.x], p0);
        atomicAdd(&g_As[d.y], p1);
        atomicAdd(&g_As[d.z], p2);
        atomicAdd(&g_As[d.w], p3);
    } else {
        for (; i < e; i++)
            atomicAdd(&g_As[dst[i]], __ldg(&g_Ps[src[i]]));
    }
}

// ---------------------------------------------------------------
// K9: per-node combine + pooled output
//   val = As*ndst + c0*s2 + c1*s1 + c2
// ---------------------------------------------------------------
__global__ void k_out(const int* __restrict__ gid, float* __restrict__ out, int n) {
    int i = blockIdx.x * blockDim.x + threadIdx.x;
    if (i >= n) return;
    float val = g_As[i] * g_ndst[i] + g_c0 * g_s2[i] + g_c1 * g_s1[i] + g_c2;
    atomicAdd(&out[gid[i]], val);
}

// ---------------------------------------------------------------
extern "C" void kernel_launch(void* const* d_in, const int* in_sizes, int n_in,
                              void* d_out, int out_size)
{
    const int* feats = (const int*)d_in[0];
    const int* src   = (const int*)d_in[1];
    const int* dst   = (const int*)d_in[2];
    const int* gid   = (const int*)d_in[3];
    int k = 4;
    if (n_in >= 9 && in_sizes[4] == 1) k = 5;
    const float* emb  = (const float*)d_in[k];
    const float* Ws   = (const float*)d_in[k + 1];
    const float* bs   = (const float*)d_in[k + 2];
    const float* wreg = (const float*)d_in[k + 3];
    float* out = (float*)d_out;

    int n = in_sizes[0];
    int e = in_sizes[1];
    int ng = out_size;
    int vocab = in_sizes[k] / HID;

    int nB  = (n + 255) / 256;
    int eB  = (e / 4 + 256) / 256;

    k_fold<<<1, HID>>>(Ws, bs, wreg);
    k_init<<<nB, 256>>>(out, n, ng);
    k_deg<<<eB, 256>>>(src, dst, e);
    k_tdot<<<(vocab * 16 + 255) / 256, 256>>>(emb, vocab);
    k_p0<<<nB, 256>>>(feats, n);

    k_prop2<<<eB, 256>>>(src, dst, e);     // S^1
    k_rescale1<<<nB, 256>>>(n);
    k_prop2<<<eB, 256>>>(src, dst, e);     // S^2
    k_rescale2<<<nB, 256>>>(n);
    k_prop1<<<eB, 256>>>(src, dst, e);     // S^3 (scalar only)
    k_out<<<nB, 256>>>(gid, out, n);
}